// round 8
// baseline (speedup 1.0000x reference)
#include <cuda_runtime.h>
#include <math.h>
#include <stdint.h>

// Problem dims
#define T_TOK 4096
#define NS    4095        // T-1 steps
#define EDIM  512
#define HDIM  1024
#define G4H   4096        // 4*H
#define NCLS  1221

// Recurrence config
#define NBLK  128         // persistent CTAs (all co-resident on 148 SMs)
#define HPB   8           // H / NBLK h-indices per CTA
#define REC_T 256         // threads per recurrence CTA

// ---------------- device scratch (no allocations allowed) ----------------
__device__ float    g_xs[NS * (2 * EDIM)];          // [4095,1024] concat inputs
__device__ float    g_xg[(size_t)NS * G4H];         // [4095,4096] x gate preacts
__device__ float    g_hs[(size_t)NS * HDIM];        // [4095,1024] hidden outputs
__device__ __align__(16) float g_hbuf[2][HDIM];     // double-buffered h state
// Private mirror flags: g_mir[consumer][producer]. Each consumer CTA polls
// only its own 512B row -> no cross-CTA line sharing, no L2 slice saturation.
__device__ __align__(128) unsigned g_mir[NBLK][NBLK];
__device__ float    g_bias[G4H];                    // b_ih + b_hh

// Acquire load: orders subsequent loads after the flag observation
// (compiler via "memory" clobber, HW via .acquire).
__device__ __forceinline__ unsigned ld_acquire(const unsigned* p) {
    unsigned v;
    asm volatile("ld.acquire.gpu.global.u32 %0, [%1];"
                 : "=r"(v) : "l"(p) : "memory");
    return v;
}

// ---------------- kernel 0: embed/concat + init ----------------
__global__ void prep_kernel(const int* __restrict__ x,
                            const float* __restrict__ emb,
                            const float* __restrict__ b_ih,
                            const float* __restrict__ b_hh) {
    int b = blockIdx.x;
    if (b < NS) {
        int tok  = x[b];
        int last = x[NS];
        const float* e0 = emb + (size_t)tok  * EDIM;
        const float* e1 = emb + (size_t)last * EDIM;
        float* dst = g_xs + (size_t)b * (2 * EDIM);
        for (int j = threadIdx.x; j < EDIM; j += blockDim.x) {
            dst[j]        = e0[j];
            dst[EDIM + j] = e1[j];
        }
    } else {
        // init block: bias sum, zero h0 (both parity rows), zero mirrors
        for (int j = threadIdx.x; j < G4H; j += blockDim.x)
            g_bias[j] = b_ih[j] + b_hh[j];
        float* hb = &g_hbuf[0][0];
        for (int j = threadIdx.x; j < 2 * HDIM; j += blockDim.x)
            hb[j] = 0.0f;
        unsigned* m = &g_mir[0][0];
        for (int j = threadIdx.x; j < NBLK * NBLK; j += blockDim.x)
            m[j] = 0u;
    }
}

// ---------------- generic SGEMM: C[m,n] = sum_k A[m,k]*B[n,k] + bias[n] ----
template <int BM, int BN, int BK, int TM, int TN, int NT>
__global__ void __launch_bounds__(NT)
sgemm_tn(const float* __restrict__ A, const float* __restrict__ B,
         const float* __restrict__ bias, float* __restrict__ C,
         int M, int N, int K) {
    __shared__ float As[BK][BM];
    __shared__ float Bs[BK][BN];

    const int m0 = blockIdx.y * BM;
    const int n0 = blockIdx.x * BN;
    const int tid = threadIdx.x;

    const int arow = tid / (BK / 4);
    const int acol = (tid % (BK / 4)) * 4;
    const int tx = tid % (BN / TN);
    const int ty = tid / (BN / TN);

    float acc[TM][TN];
#pragma unroll
    for (int i = 0; i < TM; i++)
#pragma unroll
        for (int j = 0; j < TN; j++) acc[i][j] = 0.0f;

    for (int k0 = 0; k0 < K; k0 += BK) {
        float4 av = make_float4(0.f, 0.f, 0.f, 0.f);
        if (m0 + arow < M)
            av = *(const float4*)(A + (size_t)(m0 + arow) * K + k0 + acol);
        As[acol + 0][arow] = av.x;
        As[acol + 1][arow] = av.y;
        As[acol + 2][arow] = av.z;
        As[acol + 3][arow] = av.w;

        float4 bv = make_float4(0.f, 0.f, 0.f, 0.f);
        if (n0 + arow < N)
            bv = *(const float4*)(B + (size_t)(n0 + arow) * K + k0 + acol);
        Bs[acol + 0][arow] = bv.x;
        Bs[acol + 1][arow] = bv.y;
        Bs[acol + 2][arow] = bv.z;
        Bs[acol + 3][arow] = bv.w;

        __syncthreads();

#pragma unroll
        for (int k = 0; k < BK; k++) {
            float ar[TM], br[TN];
#pragma unroll
            for (int i = 0; i < TM; i++) ar[i] = As[k][ty * TM + i];
#pragma unroll
            for (int j = 0; j < TN; j++) br[j] = Bs[k][tx * TN + j];
#pragma unroll
            for (int i = 0; i < TM; i++)
#pragma unroll
                for (int j = 0; j < TN; j++)
                    acc[i][j] = fmaf(ar[i], br[j], acc[i][j]);
        }
        __syncthreads();
    }

#pragma unroll
    for (int i = 0; i < TM; i++) {
        int m = m0 + ty * TM + i;
        if (m >= M) continue;
#pragma unroll
        for (int j = 0; j < TN; j++) {
            int n = n0 + tx * TN + j;
            if (n < N) C[(size_t)m * N + n] = acc[i][j] + bias[n];
        }
    }
}

// ---------------- persistent LSTM recurrence ----------------
// CTA b owns h-indices [8b, 8b+8): 32 rows of W_hh in registers.
// Sync: proven release (stcg h -> per-lane fence -> syncwarp -> flag store),
// fanned out to per-consumer private mirror flags. Consumers acquire-poll
// their private slot, then load. Warps 1-7 bar.arrive past the reduction so
// h(t+1) staging overlaps warp 0's epilogue.
__global__ void __launch_bounds__(REC_T, 1)
lstm_rec(const float* __restrict__ Whh) {
    __shared__ float4 h4_s[HDIM / 4];     // staged h(t)
    __shared__ float red[2][32];          // warp dot results (parity)
    __shared__ float xg_s[2][32];         // x-gate slice (parity)

    const int b = blockIdx.x;
    const int tid = threadIdx.x;
    const int base = b * HPB;
    const int w = tid >> 5;
    const int l = tid & 31;

    // Weight slice: rows r = 4w..4w+3 (gate = r>>3, idx = r&7),
    // lane l holds k-elements l, l+32, ..., l+992 (coalesced loads).
    float wreg[4][32];
#pragma unroll
    for (int rr = 0; rr < 4; rr++) {
        int r = 4 * w + rr;
        int grow = (r >> 3) * HDIM + base + (r & 7);
        const float* wp = Whh + (size_t)grow * HDIM;
#pragma unroll
        for (int i = 0; i < 32; i++) wreg[rr][i] = wp[l + 32 * i];
    }

    float c_reg = 0.0f;                   // cell state (warp 0, lanes 0..7)

    // prefetch xg(0) into a register (warp 7)
    float xg_next = 0.0f;
    const int xr = tid - 224;             // 0..31 for warp 7
    if (tid >= 224)
        xg_next = __ldcg(&g_xg[(size_t)0 * G4H + (xr >> 3) * HDIM + base + (xr & 7)]);

    // this thread's PRIVATE mirror of its producer's flag
    const unsigned* myflag = &g_mir[b][tid >> 1];

    for (int t = 0; t < NS; t++) {
        const int p = t & 1;

        // commit prefetched xg(t); issue prefetch of xg(t+1)
        if (tid >= 224) {
            xg_s[p][xr] = xg_next;
            if (t + 1 < NS)
                xg_next = __ldcg(&g_xg[(size_t)(t + 1) * G4H +
                                       (xr >> 3) * HDIM + base + (xr & 7)]);
        }

        // acquire-wait on private mirror, then load my float4 h slice
        if (t > 0) {
            while (ld_acquire(myflag) < (unsigned)t) { }
        }
        h4_s[tid] = __ldcg(((const float4*)&g_hbuf[t & 1][0]) + tid);
        __syncthreads();                  // barrier #1: h_s fully staged

        // 4 dot products per warp (rows 4w..4w+3) over H=1024
        const float* h_s = (const float*)h4_s;
        float a0 = 0.f, a1 = 0.f, a2 = 0.f, a3 = 0.f;
#pragma unroll
        for (int i = 0; i < 32; i++) {
            float hv = h_s[l + 32 * i];
            a0 = fmaf(wreg[0][i], hv, a0);
            a1 = fmaf(wreg[1][i], hv, a1);
            a2 = fmaf(wreg[2][i], hv, a2);
            a3 = fmaf(wreg[3][i], hv, a3);
        }
#pragma unroll
        for (int off = 16; off; off >>= 1) {
            a0 += __shfl_down_sync(0xffffffffu, a0, off);
            a1 += __shfl_down_sync(0xffffffffu, a1, off);
            a2 += __shfl_down_sync(0xffffffffu, a2, off);
            a3 += __shfl_down_sync(0xffffffffu, a3, off);
        }
        if (l == 0) {
            red[p][4 * w + 0] = a0;
            red[p][4 * w + 1] = a1;
            red[p][4 * w + 2] = a2;
            red[p][4 * w + 3] = a3;
        }

        // warps 1-7: arrive and run ahead (poll + stage h(t+1) overlaps the
        // epilogue). warp 0: wait for all red, then do the epilogue.
        if (w != 0) {
            asm volatile("bar.arrive 3, %0;" :: "r"(REC_T) : "memory");
        } else {
            asm volatile("bar.sync 3, %0;" :: "r"(REC_T) : "memory");

            // epilogue: one activation per lane (accurate expf/tanhf)
            float pre = red[p][l] + xg_s[p][l];
            float act = ((l >> 3) == 2) ? tanhf(pre)
                                        : 1.0f / (1.0f + expf(-pre));
            int j = l & 7;
            float iv = __shfl_sync(0xffffffffu, act, j);
            float fv = __shfl_sync(0xffffffffu, act, j + 8);
            float gv = __shfl_sync(0xffffffffu, act, j + 16);
            float ov = __shfl_sync(0xffffffffu, act, j + 24);
            float hh = 0.0f;
            if (l < 8) {
                c_reg = fv * c_reg + iv * gv;
                hh = ov * tanhf(c_reg);
                __stcg(&g_hbuf[(t + 1) & 1][base + j], hh);
                __threadfence();          // release: h visible before flags
            }
            __syncwarp();
            // fan out the step counter to all consumers' private mirrors
            {
                unsigned v = (unsigned)(t + 1);
#pragma unroll
                for (int q = 0; q < NBLK / 32; q++)
                    *(volatile unsigned*)&g_mir[l + 32 * q][b] = v;
            }
            if (l < 8)                    // history store off critical path
                g_hs[(size_t)t * HDIM + base + j] = hh;
        }
        // red/xg_s parity-buffered; h4_s(t+1) writes gated by each thread's
        // own acquire-poll (which requires this CTA's epilogue for its slice).
    }
}

// ---------------- launch ----------------
extern "C" void kernel_launch(void* const* d_in, const int* in_sizes, int n_in,
                              void* d_out, int out_size) {
    const int*   x     = (const int*)d_in[0];
    const float* emb   = (const float*)d_in[1];
    const float* W_ih  = (const float*)d_in[2];
    const float* W_hh  = (const float*)d_in[3];
    const float* b_ih  = (const float*)d_in[4];
    const float* b_hh  = (const float*)d_in[5];
    const float* W_out = (const float*)d_in[6];
    const float* b_out = (const float*)d_in[7];
    float* out = (float*)d_out;

    float *p_xs, *p_xg, *p_hs, *p_bias;
    cudaGetSymbolAddress((void**)&p_xs, g_xs);
    cudaGetSymbolAddress((void**)&p_xg, g_xg);
    cudaGetSymbolAddress((void**)&p_hs, g_hs);
    cudaGetSymbolAddress((void**)&p_bias, g_bias);

    // 0) embed + concat + init state/mirrors/bias
    prep_kernel<<<NS + 1, 256>>>(x, emb, b_ih, b_hh);

    // 1) x_gates = xs @ W_ih^T + (b_ih+b_hh)   [4095 x 4096]
    {
        dim3 grid(G4H / 128, (NS + 127) / 128);
        sgemm_tn<128, 128, 8, 8, 8, 256><<<grid, 256>>>(
            p_xs, W_ih, p_bias, p_xg, NS, G4H, 2 * EDIM);
    }

    // 2) serial LSTM scan (persistent cooperative kernel)
    lstm_rec<<<NBLK, REC_T>>>(W_hh);

    // 3) out = hs @ W_out^T + b_out   [4095 x 1221]
    {
        dim3 grid((NCLS + 127) / 128, (NS + 127) / 128);
        sgemm_tn<128, 128, 8, 8, 8, 256><<<grid, 256>>>(
            p_hs, W_out, b_out, out, NS, NCLS, HDIM);
    }
}

// round 9
// speedup vs baseline: 1.3765x; 1.3765x over previous
#include <cuda_runtime.h>
#include <math.h>
#include <stdint.h>

// Problem dims
#define T_TOK 4096
#define NS    4095        // T-1 steps
#define EDIM  512
#define HDIM  1024
#define G4H   4096        // 4*H
#define NCLS  1221

// Recurrence config
#define NBLK  128         // persistent CTAs (all co-resident on 148 SMs)
#define HPB   8           // H / NBLK h-indices per CTA
#define REC_T 256         // threads per recurrence CTA
#define FPAD  32          // flag padding: one flag per 128B L2 line

// ---------------- device scratch (no allocations allowed) ----------------
__device__ float    g_xs[NS * (2 * EDIM)];          // [4095,1024] concat inputs
__device__ float    g_xg[(size_t)NS * G4H];         // [4095,4096] x gate preacts
__device__ float    g_hs[(size_t)NS * HDIM];        // [4095,1024] hidden outputs
__device__ __align__(16) float g_hbuf[2][HDIM];     // double-buffered h state
__device__ unsigned g_flags[NBLK * FPAD];           // padded monotonic counters
__device__ float    g_bias[G4H];                    // b_ih + b_hh

// Acquire load: orders subsequent loads after the flag observation
// (compiler via "memory" clobber, HW via .acquire).
__device__ __forceinline__ unsigned ld_acquire(const unsigned* p) {
    unsigned v;
    asm volatile("ld.acquire.gpu.global.u32 %0, [%1];"
                 : "=r"(v) : "l"(p) : "memory");
    return v;
}

// Packed dual-FMA (FFMA2): d = a*b + c on two f32 lanes of a 64-bit reg.
__device__ __forceinline__ unsigned long long ffma2(unsigned long long a,
                                                    unsigned long long b,
                                                    unsigned long long c) {
    unsigned long long d;
    asm("fma.rn.f32x2 %0, %1, %2, %3;" : "=l"(d) : "l"(a), "l"(b), "l"(c));
    return d;
}
__device__ __forceinline__ float f2_lo(unsigned long long v) {
    return __uint_as_float((unsigned)(v & 0xffffffffull));
}
__device__ __forceinline__ float f2_hi(unsigned long long v) {
    return __uint_as_float((unsigned)(v >> 32));
}

// ---------------- kernel 0: embed/concat + init ----------------
__global__ void prep_kernel(const int* __restrict__ x,
                            const float* __restrict__ emb,
                            const float* __restrict__ b_ih,
                            const float* __restrict__ b_hh) {
    int b = blockIdx.x;
    if (b < NS) {
        int tok  = x[b];
        int last = x[NS];
        const float* e0 = emb + (size_t)tok  * EDIM;
        const float* e1 = emb + (size_t)last * EDIM;
        float* dst = g_xs + (size_t)b * (2 * EDIM);
        for (int j = threadIdx.x; j < EDIM; j += blockDim.x) {
            dst[j]        = e0[j];
            dst[EDIM + j] = e1[j];
        }
    } else {
        // init block: bias sum, zero h0 (both parity rows), zero flags
        for (int j = threadIdx.x; j < G4H; j += blockDim.x)
            g_bias[j] = b_ih[j] + b_hh[j];
        float* hb = &g_hbuf[0][0];
        for (int j = threadIdx.x; j < 2 * HDIM; j += blockDim.x)
            hb[j] = 0.0f;
        for (int j = threadIdx.x; j < NBLK * FPAD; j += blockDim.x)
            g_flags[j] = 0u;
    }
}

// ---------------- generic SGEMM: C[m,n] = sum_k A[m,k]*B[n,k] + bias[n] ----
template <int BM, int BN, int BK, int TM, int TN, int NT>
__global__ void __launch_bounds__(NT)
sgemm_tn(const float* __restrict__ A, const float* __restrict__ B,
         const float* __restrict__ bias, float* __restrict__ C,
         int M, int N, int K) {
    __shared__ float As[BK][BM];
    __shared__ float Bs[BK][BN];

    const int m0 = blockIdx.y * BM;
    const int n0 = blockIdx.x * BN;
    const int tid = threadIdx.x;

    const int arow = tid / (BK / 4);
    const int acol = (tid % (BK / 4)) * 4;
    const int tx = tid % (BN / TN);
    const int ty = tid / (BN / TN);

    float acc[TM][TN];
#pragma unroll
    for (int i = 0; i < TM; i++)
#pragma unroll
        for (int j = 0; j < TN; j++) acc[i][j] = 0.0f;

    for (int k0 = 0; k0 < K; k0 += BK) {
        float4 av = make_float4(0.f, 0.f, 0.f, 0.f);
        if (m0 + arow < M)
            av = *(const float4*)(A + (size_t)(m0 + arow) * K + k0 + acol);
        As[acol + 0][arow] = av.x;
        As[acol + 1][arow] = av.y;
        As[acol + 2][arow] = av.z;
        As[acol + 3][arow] = av.w;

        float4 bv = make_float4(0.f, 0.f, 0.f, 0.f);
        if (n0 + arow < N)
            bv = *(const float4*)(B + (size_t)(n0 + arow) * K + k0 + acol);
        Bs[acol + 0][arow] = bv.x;
        Bs[acol + 1][arow] = bv.y;
        Bs[acol + 2][arow] = bv.z;
        Bs[acol + 3][arow] = bv.w;

        __syncthreads();

#pragma unroll
        for (int k = 0; k < BK; k++) {
            float ar[TM], br[TN];
#pragma unroll
            for (int i = 0; i < TM; i++) ar[i] = As[k][ty * TM + i];
#pragma unroll
            for (int j = 0; j < TN; j++) br[j] = Bs[k][tx * TN + j];
#pragma unroll
            for (int i = 0; i < TM; i++)
#pragma unroll
                for (int j = 0; j < TN; j++)
                    acc[i][j] = fmaf(ar[i], br[j], acc[i][j]);
        }
        __syncthreads();
    }

#pragma unroll
    for (int i = 0; i < TM; i++) {
        int m = m0 + ty * TM + i;
        if (m >= M) continue;
#pragma unroll
        for (int j = 0; j < TN; j++) {
            int n = n0 + tx * TN + j;
            if (n < N) C[(size_t)m * N + n] = acc[i][j] + bias[n];
        }
    }
}

// ---------------- persistent LSTM recurrence ----------------
// R7-proven sync (shared padded flags, acquire fused poll+load, proven
// release) + FFMA2 packed dot products + run-ahead barrier split (warps
// 1-7 bar.arrive past the reduction; warp 0 runs the epilogue).
__global__ void __launch_bounds__(REC_T, 1)
lstm_rec(const float* __restrict__ Whh) {
    __shared__ float4 h4_s[HDIM / 4];     // staged h(t)
    __shared__ float red[2][32];          // warp dot results (parity)
    __shared__ float xg_s[2][32];         // x-gate slice (parity)

    const int b = blockIdx.x;
    const int tid = threadIdx.x;
    const int base = b * HPB;
    const int w = tid >> 5;
    const int l = tid & 31;

    // Weight slice as f32x2: rows r = 4w..4w+3 (gate = r>>3, idx = r&7),
    // lane l holds k-pairs (2(l+32i), 2(l+32i)+1), i = 0..15.
    unsigned long long wreg[4][16];
#pragma unroll
    for (int rr = 0; rr < 4; rr++) {
        int r = 4 * w + rr;
        int grow = (r >> 3) * HDIM + base + (r & 7);
        const unsigned long long* wp =
            (const unsigned long long*)(Whh + (size_t)grow * HDIM);
#pragma unroll
        for (int i = 0; i < 16; i++) wreg[rr][i] = wp[l + 32 * i];
    }

    float c_reg = 0.0f;                   // cell state (warp 0, lanes 0..7)

    // prefetch xg(0) into a register (warp 7)
    float xg_next = 0.0f;
    const int xr = tid - 224;             // 0..31 for warp 7
    if (tid >= 224)
        xg_next = __ldcg(&g_xg[(size_t)0 * G4H + (xr >> 3) * HDIM + base + (xr & 7)]);

    // this thread's producer flag (CTA tid>>1 produces its float4 slice)
    const unsigned* myflag = &g_flags[(tid >> 1) * FPAD];

    for (int t = 0; t < NS; t++) {
        const int p = t & 1;

        // commit prefetched xg(t); issue prefetch of xg(t+1)
        if (tid >= 224) {
            xg_s[p][xr] = xg_next;
            if (t + 1 < NS)
                xg_next = __ldcg(&g_xg[(size_t)(t + 1) * G4H +
                                       (xr >> 3) * HDIM + base + (xr & 7)]);
        }

        // acquire-wait for my producer CTA, then load my float4 h slice
        if (t > 0) {
            while (ld_acquire(myflag) < (unsigned)t) { }
        }
        h4_s[tid] = __ldcg(((const float4*)&g_hbuf[t & 1][0]) + tid);
        __syncthreads();                  // barrier #1: h_s fully staged

        // 4 rows per warp, packed f32x2 dot products over H=1024
        const unsigned long long* h2 = (const unsigned long long*)h4_s;
        unsigned long long a0 = 0, a1 = 0, a2 = 0, a3 = 0;
#pragma unroll
        for (int i = 0; i < 16; i++) {
            unsigned long long hp = h2[l + 32 * i];
            a0 = ffma2(wreg[0][i], hp, a0);
            a1 = ffma2(wreg[1][i], hp, a1);
            a2 = ffma2(wreg[2][i], hp, a2);
            a3 = ffma2(wreg[3][i], hp, a3);
        }
        float s0 = f2_lo(a0) + f2_hi(a0);
        float s1 = f2_lo(a1) + f2_hi(a1);
        float s2 = f2_lo(a2) + f2_hi(a2);
        float s3 = f2_lo(a3) + f2_hi(a3);
#pragma unroll
        for (int off = 16; off; off >>= 1) {
            s0 += __shfl_down_sync(0xffffffffu, s0, off);
            s1 += __shfl_down_sync(0xffffffffu, s1, off);
            s2 += __shfl_down_sync(0xffffffffu, s2, off);
            s3 += __shfl_down_sync(0xffffffffu, s3, off);
        }
        if (l == 0) {
            red[p][4 * w + 0] = s0;
            red[p][4 * w + 1] = s1;
            red[p][4 * w + 2] = s2;
            red[p][4 * w + 3] = s3;
        }

        // warps 1-7: arrive and run ahead (poll + stage h(t+1) overlaps the
        // epilogue). warp 0: wait for all red, then do the epilogue.
        if (w != 0) {
            asm volatile("bar.arrive 3, %0;" :: "r"(REC_T) : "memory");
        } else {
            asm volatile("bar.sync 3, %0;" :: "r"(REC_T) : "memory");

            // epilogue: one activation per lane (accurate expf/tanhf)
            float pre = red[p][l] + xg_s[p][l];
            float act = ((l >> 3) == 2) ? tanhf(pre)
                                        : 1.0f / (1.0f + expf(-pre));
            int j = l & 7;
            float iv = __shfl_sync(0xffffffffu, act, j);
            float fv = __shfl_sync(0xffffffffu, act, j + 8);
            float gv = __shfl_sync(0xffffffffu, act, j + 16);
            float ov = __shfl_sync(0xffffffffu, act, j + 24);
            float hh = 0.0f;
            if (l < 8) {
                c_reg = fv * c_reg + iv * gv;
                hh = ov * tanhf(c_reg);
                __stcg(&g_hbuf[(t + 1) & 1][base + j], hh);
                __threadfence();          // release: h visible before flag
            }
            __syncwarp();
            if (l == 0)
                *(volatile unsigned*)&g_flags[b * FPAD] = (unsigned)(t + 1);
            if (l < 8)                    // history store off critical path
                g_hs[(size_t)t * HDIM + base + j] = hh;
        }
        // red/xg_s parity-buffered; h4_s(t+1) writes gated by each thread's
        // own acquire-poll; run-ahead bounded to 1 step by barrier #1.
    }
}

// ---------------- launch ----------------
extern "C" void kernel_launch(void* const* d_in, const int* in_sizes, int n_in,
                              void* d_out, int out_size) {
    const int*   x     = (const int*)d_in[0];
    const float* emb   = (const float*)d_in[1];
    const float* W_ih  = (const float*)d_in[2];
    const float* W_hh  = (const float*)d_in[3];
    const float* b_ih  = (const float*)d_in[4];
    const float* b_hh  = (const float*)d_in[5];
    const float* W_out = (const float*)d_in[6];
    const float* b_out = (const float*)d_in[7];
    float* out = (float*)d_out;

    float *p_xs, *p_xg, *p_hs, *p_bias;
    cudaGetSymbolAddress((void**)&p_xs, g_xs);
    cudaGetSymbolAddress((void**)&p_xg, g_xg);
    cudaGetSymbolAddress((void**)&p_hs, g_hs);
    cudaGetSymbolAddress((void**)&p_bias, g_bias);

    // 0) embed + concat + init state/flags/bias
    prep_kernel<<<NS + 1, 256>>>(x, emb, b_ih, b_hh);

    // 1) x_gates = xs @ W_ih^T + (b_ih+b_hh)   [4095 x 4096]
    {
        dim3 grid(G4H / 128, (NS + 127) / 128);
        sgemm_tn<128, 128, 8, 8, 8, 256><<<grid, 256>>>(
            p_xs, W_ih, p_bias, p_xg, NS, G4H, 2 * EDIM);
    }

    // 2) serial LSTM scan (persistent cooperative kernel)
    lstm_rec<<<NBLK, REC_T>>>(W_hh);

    // 3) out = hs @ W_out^T + b_out   [4095 x 1221]
    {
        dim3 grid((NCLS + 127) / 128, (NS + 127) / 128);
        sgemm_tn<128, 128, 8, 8, 8, 256><<<grid, 256>>>(
            p_hs, W_out, b_out, out, NS, NCLS, HDIM);
    }
}

// round 13
// speedup vs baseline: 1.4705x; 1.0683x over previous
#include <cuda_runtime.h>
#include <math.h>
#include <stdint.h>

// Problem dims
#define T_TOK 4096
#define NS    4095        // T-1 steps
#define EDIM  512
#define HDIM  1024
#define G4H   4096        // 4*H
#define NCLS  1221

// Recurrence config
#define NBLK  128         // persistent CTAs (all co-resident on 148 SMs)
#define HPB   8           // H / NBLK h-indices per CTA
#define REC_T 256         // threads per recurrence CTA
#define FPAD  32          // flag padding: one flag per 128B L2 line

// ---------------- device scratch (no allocations allowed) ----------------
__device__ float    g_xs[NS * (2 * EDIM)];          // [4095,1024] concat inputs
__device__ float    g_xg[(size_t)NS * G4H];         // [4095,4096] x gate preacts
__device__ float    g_hs[(size_t)NS * HDIM];        // [4095,1024] hidden outputs
__device__ __align__(16) float g_hbuf[2][HDIM];     // double-buffered h state
__device__ unsigned g_flags[NBLK * FPAD];           // padded monotonic counters
__device__ float    g_bias[G4H];                    // b_ih + b_hh

// Acquire load: orders subsequent loads after the flag observation
// (compiler via "memory" clobber, HW via .acquire).
__device__ __forceinline__ unsigned ld_acquire(const unsigned* p) {
    unsigned v;
    asm volatile("ld.acquire.gpu.global.u32 %0, [%1];"
                 : "=r"(v) : "l"(p) : "memory");
    return v;
}

// Packed dual-FMA (FFMA2): d = a*b + c on two f32 lanes of a 64-bit reg.
__device__ __forceinline__ unsigned long long ffma2(unsigned long long a,
                                                    unsigned long long b,
                                                    unsigned long long c) {
    unsigned long long d;
    asm("fma.rn.f32x2 %0, %1, %2, %3;" : "=l"(d) : "l"(a), "l"(b), "l"(c));
    return d;
}
__device__ __forceinline__ float f2_lo(unsigned long long v) {
    return __uint_as_float((unsigned)(v & 0xffffffffull));
}
__device__ __forceinline__ float f2_hi(unsigned long long v) {
    return __uint_as_float((unsigned)(v >> 32));
}

// ---------------- kernel 0: embed/concat + init ----------------
__global__ void prep_kernel(const int* __restrict__ x,
                            const float* __restrict__ emb,
                            const float* __restrict__ b_ih,
                            const float* __restrict__ b_hh) {
    int b = blockIdx.x;
    if (b < NS) {
        int tok  = x[b];
        int last = x[NS];
        const float* e0 = emb + (size_t)tok  * EDIM;
        const float* e1 = emb + (size_t)last * EDIM;
        float* dst = g_xs + (size_t)b * (2 * EDIM);
        for (int j = threadIdx.x; j < EDIM; j += blockDim.x) {
            dst[j]        = e0[j];
            dst[EDIM + j] = e1[j];
        }
    } else {
        // init block: bias sum, zero h0 (both parity rows), zero flags
        for (int j = threadIdx.x; j < G4H; j += blockDim.x)
            g_bias[j] = b_ih[j] + b_hh[j];
        float* hb = &g_hbuf[0][0];
        for (int j = threadIdx.x; j < 2 * HDIM; j += blockDim.x)
            hb[j] = 0.0f;
        for (int j = threadIdx.x; j < NBLK * FPAD; j += blockDim.x)
            g_flags[j] = 0u;
    }
}

// ---------------- generic SGEMM: C[m,n] = sum_k A[m,k]*B[n,k] + bias[n] ----
template <int BM, int BN, int BK, int TM, int TN, int NT>
__global__ void __launch_bounds__(NT)
sgemm_tn(const float* __restrict__ A, const float* __restrict__ B,
         const float* __restrict__ bias, float* __restrict__ C,
         int M, int N, int K) {
    __shared__ float As[BK][BM];
    __shared__ float Bs[BK][BN];

    const int m0 = blockIdx.y * BM;
    const int n0 = blockIdx.x * BN;
    const int tid = threadIdx.x;

    const int arow = tid / (BK / 4);
    const int acol = (tid % (BK / 4)) * 4;
    const int tx = tid % (BN / TN);
    const int ty = tid / (BN / TN);

    float acc[TM][TN];
#pragma unroll
    for (int i = 0; i < TM; i++)
#pragma unroll
        for (int j = 0; j < TN; j++) acc[i][j] = 0.0f;

    for (int k0 = 0; k0 < K; k0 += BK) {
        float4 av = make_float4(0.f, 0.f, 0.f, 0.f);
        if (m0 + arow < M)
            av = *(const float4*)(A + (size_t)(m0 + arow) * K + k0 + acol);
        As[acol + 0][arow] = av.x;
        As[acol + 1][arow] = av.y;
        As[acol + 2][arow] = av.z;
        As[acol + 3][arow] = av.w;

        float4 bv = make_float4(0.f, 0.f, 0.f, 0.f);
        if (n0 + arow < N)
            bv = *(const float4*)(B + (size_t)(n0 + arow) * K + k0 + acol);
        Bs[acol + 0][arow] = bv.x;
        Bs[acol + 1][arow] = bv.y;
        Bs[acol + 2][arow] = bv.z;
        Bs[acol + 3][arow] = bv.w;

        __syncthreads();

#pragma unroll
        for (int k = 0; k < BK; k++) {
            float ar[TM], br[TN];
#pragma unroll
            for (int i = 0; i < TM; i++) ar[i] = As[k][ty * TM + i];
#pragma unroll
            for (int j = 0; j < TN; j++) br[j] = Bs[k][tx * TN + j];
#pragma unroll
            for (int i = 0; i < TM; i++)
#pragma unroll
                for (int j = 0; j < TN; j++)
                    acc[i][j] = fmaf(ar[i], br[j], acc[i][j]);
        }
        __syncthreads();
    }

#pragma unroll
    for (int i = 0; i < TM; i++) {
        int m = m0 + ty * TM + i;
        if (m >= M) continue;
#pragma unroll
        for (int j = 0; j < TN; j++) {
            int n = n0 + tx * TN + j;
            if (n < N) C[(size_t)m * N + n] = acc[i][j] + bias[n];
        }
    }
}

// ---------------- persistent LSTM recurrence ----------------
// R7-proven sync protocol; consumer-side traffic reduction:
// only even lanes poll (1 poller per producer per CTA), odd lanes get
// ordering via __syncwarp after the partner's acquire; __nanosleep backoff
// only after a failed probe. Release sequence unchanged (proven).
__global__ void __launch_bounds__(REC_T, 1)
lstm_rec(const float* __restrict__ Whh) {
    __shared__ float4 h4_s[HDIM / 4];     // staged h(t)
    __shared__ float red[2][32];          // warp dot results (parity)
    __shared__ float xg_s[2][32];         // x-gate slice (parity)

    const int b = blockIdx.x;
    const int tid = threadIdx.x;
    const int base = b * HPB;
    const int w = tid >> 5;
    const int l = tid & 31;

    // Weight slice as f32x2: rows r = 4w..4w+3 (gate = r>>3, idx = r&7),
    // lane l holds k-pairs (2(l+32i), 2(l+32i)+1), i = 0..15.
    unsigned long long wreg[4][16];
#pragma unroll
    for (int rr = 0; rr < 4; rr++) {
        int r = 4 * w + rr;
        int grow = (r >> 3) * HDIM + base + (r & 7);
        const unsigned long long* wp =
            (const unsigned long long*)(Whh + (size_t)grow * HDIM);
#pragma unroll
        for (int i = 0; i < 16; i++) wreg[rr][i] = wp[l + 32 * i];
    }

    float c_reg = 0.0f;                   // cell state (warp 0, lanes 0..7)

    // prefetch xg(0) into a register (warp 7)
    float xg_next = 0.0f;
    const int xr = tid - 224;             // 0..31 for warp 7
    if (tid >= 224)
        xg_next = __ldcg(&g_xg[(size_t)0 * G4H + (xr >> 3) * HDIM + base + (xr & 7)]);

    // this thread's producer flag (CTA tid>>1 produces its float4 slice)
    const unsigned* myflag = &g_flags[(tid >> 1) * FPAD];

    for (int t = 0; t < NS; t++) {
        const int p = t & 1;

        // commit prefetched xg(t); issue prefetch of xg(t+1)
        if (tid >= 224) {
            xg_s[p][xr] = xg_next;
            if (t + 1 < NS)
                xg_next = __ldcg(&g_xg[(size_t)(t + 1) * G4H +
                                       (xr >> 3) * HDIM + base + (xr & 7)]);
        }

        // even lanes poll (acquire); odd lanes inherit ordering via syncwarp.
        // Backoff only after a failed probe (fast path: zero extra cost).
        if (t > 0) {
            if ((tid & 1) == 0) {
                if (ld_acquire(myflag) < (unsigned)t) {
                    do {
                        __nanosleep(100);
                    } while (ld_acquire(myflag) < (unsigned)t);
                }
            }
            __syncwarp();
        }
        h4_s[tid] = __ldcg(((const float4*)&g_hbuf[t & 1][0]) + tid);
        __syncthreads();                  // barrier #1: h_s fully staged

        // 4 rows per warp, packed f32x2 dot products over H=1024
        const unsigned long long* h2 = (const unsigned long long*)h4_s;
        unsigned long long a0 = 0, a1 = 0, a2 = 0, a3 = 0;
#pragma unroll
        for (int i = 0; i < 16; i++) {
            unsigned long long hp = h2[l + 32 * i];
            a0 = ffma2(wreg[0][i], hp, a0);
            a1 = ffma2(wreg[1][i], hp, a1);
            a2 = ffma2(wreg[2][i], hp, a2);
            a3 = ffma2(wreg[3][i], hp, a3);
        }
        float s0 = f2_lo(a0) + f2_hi(a0);
        float s1 = f2_lo(a1) + f2_hi(a1);
        float s2 = f2_lo(a2) + f2_hi(a2);
        float s3 = f2_lo(a3) + f2_hi(a3);
#pragma unroll
        for (int off = 16; off; off >>= 1) {
            s0 += __shfl_down_sync(0xffffffffu, s0, off);
            s1 += __shfl_down_sync(0xffffffffu, s1, off);
            s2 += __shfl_down_sync(0xffffffffu, s2, off);
            s3 += __shfl_down_sync(0xffffffffu, s3, off);
        }
        if (l == 0) {
            red[p][4 * w + 0] = s0;
            red[p][4 * w + 1] = s1;
            red[p][4 * w + 2] = s2;
            red[p][4 * w + 3] = s3;
        }

        // warps 1-7: arrive and run ahead (poll + stage h(t+1) overlaps the
        // epilogue). warp 0: wait for all red, then do the epilogue.
        if (w != 0) {
            asm volatile("bar.arrive 3, %0;" :: "r"(REC_T) : "memory");
        } else {
            asm volatile("bar.sync 3, %0;" :: "r"(REC_T) : "memory");

            // epilogue: one activation per lane (accurate expf/tanhf)
            float pre = red[p][l] + xg_s[p][l];
            float act = ((l >> 3) == 2) ? tanhf(pre)
                                        : 1.0f / (1.0f + expf(-pre));
            int j = l & 7;
            float iv = __shfl_sync(0xffffffffu, act, j);
            float fv = __shfl_sync(0xffffffffu, act, j + 8);
            float gv = __shfl_sync(0xffffffffu, act, j + 16);
            float ov = __shfl_sync(0xffffffffu, act, j + 24);
            float hh = 0.0f;
            if (l < 8) {
                c_reg = fv * c_reg + iv * gv;
                hh = ov * tanhf(c_reg);
                __stcg(&g_hbuf[(t + 1) & 1][base + j], hh);
                __threadfence();          // release: h visible before flag
            }
            __syncwarp();
            if (l == 0)
                *(volatile unsigned*)&g_flags[b * FPAD] = (unsigned)(t + 1);
            if (l < 8)                    // history store off critical path
                g_hs[(size_t)t * HDIM + base + j] = hh;
        }
        // red/xg_s parity-buffered; h4_s(t+1) writes gated by each thread's
        // own (or partner's) acquire-poll; run-ahead bounded by barrier #1.
    }
}

// ---------------- launch ----------------
extern "C" void kernel_launch(void* const* d_in, const int* in_sizes, int n_in,
                              void* d_out, int out_size) {
    const int*   x     = (const int*)d_in[0];
    const float* emb   = (const float*)d_in[1];
    const float* W_ih  = (const float*)d_in[2];
    const float* W_hh  = (const float*)d_in[3];
    const float* b_ih  = (const float*)d_in[4];
    const float* b_hh  = (const float*)d_in[5];
    const float* W_out = (const float*)d_in[6];
    const float* b_out = (const float*)d_in[7];
    float* out = (float*)d_out;

    float *p_xs, *p_xg, *p_hs, *p_bias;
    cudaGetSymbolAddress((void**)&p_xs, g_xs);
    cudaGetSymbolAddress((void**)&p_xg, g_xg);
    cudaGetSymbolAddress((void**)&p_hs, g_hs);
    cudaGetSymbolAddress((void**)&p_bias, g_bias);

    // 0) embed + concat + init state/flags/bias
    prep_kernel<<<NS + 1, 256>>>(x, emb, b_ih, b_hh);

    // 1) x_gates = xs @ W_ih^T + (b_ih+b_hh)   [4095 x 4096]
    {
        dim3 grid(G4H / 128, (NS + 127) / 128);
        sgemm_tn<128, 128, 8, 8, 8, 256><<<grid, 256>>>(
            p_xs, W_ih, p_bias, p_xg, NS, G4H, 2 * EDIM);
    }

    // 2) serial LSTM scan (persistent cooperative kernel)
    lstm_rec<<<NBLK, REC_T>>>(W_hh);

    // 3) out = hs @ W_out^T + b_out   [4095 x 1221]
    {
        dim3 grid((NCLS + 127) / 128, (NS + 127) / 128);
        sgemm_tn<128, 128, 8, 8, 8, 256><<<grid, 256>>>(
            p_hs, W_out, b_out, out, NS, NCLS, HDIM);
    }
}